// round 2
// baseline (speedup 1.0000x reference)
#include <cuda_runtime.h>
#include <cuda_bf16.h>

#define HDIM 16
#define UDIM 7
#define HID  64
#define TMAX 100000
#define DTC  (5.0f / 60.0f)

// Scratch (no allocs allowed): precomputed input projection and h history.
__device__ float g_pu[TMAX * HID];   // b1 + W1u @ u_t, laid out [t][64]
__device__ float g_h[TMAX * HDIM];   // h_t (pre-step state), [t][16]

// ---------- packed f32x2 helpers (FFMA2 — ptxas won't auto-fuse) ----------
__device__ __forceinline__ unsigned long long pk2(float x, float y) {
    unsigned long long r;
    asm("mov.b64 %0, {%1, %2};" : "=l"(r) : "f"(x), "f"(y));
    return r;
}
__device__ __forceinline__ void upk2(unsigned long long v, float& x, float& y) {
    asm("mov.b64 {%0, %1}, %2;" : "=f"(x), "=f"(y) : "l"(v));
}
__device__ __forceinline__ unsigned long long ffma2(unsigned long long a,
                                                    unsigned long long b,
                                                    unsigned long long c) {
    unsigned long long d;
    asm("fma.rn.f32x2 %0, %1, %2, %3;" : "=l"(d) : "l"(a), "l"(b), "l"(c));
    return d;
}

// ---------- pre-pass: g_pu[t][i] = b1[i] + sum_k W1[i][16+k] * U[t][k] ----------
__global__ void pre_kernel(const float* __restrict__ U,
                           const float* __restrict__ W1,
                           const float* __restrict__ b1, int T) {
    int idx = blockIdx.x * blockDim.x + threadIdx.x;
    if (idx >= T * HID) return;
    int t = idx >> 6;
    int i = idx & 63;
    const float* u = U + t * UDIM;
    const float* w = W1 + i * (HDIM + UDIM) + HDIM;
    float s = b1[i];
#pragma unroll
    for (int k = 0; k < UDIM; k++) s = fmaf(w[k], u[k], s);
    g_pu[idx] = s;
}

// ---------- sequential scan: 1 block, 64 threads, weights in registers ----------
__global__ void __launch_bounds__(64, 1) seq_kernel(
    const float* __restrict__ W1, const float* __restrict__ b2v,
    const float* __restrict__ W2, const float* __restrict__ W3,
    const float* __restrict__ b3, const float* __restrict__ h0,
    float* __restrict__ out, int T) {
    __shared__ float4 s_h4[HDIM / 4];
    __shared__ float4 s_z1[HID / 4];
    __shared__ float4 s_z2[HID / 4];
    __shared__ float  s_dhp[HDIM];
    float* sh_h = (float*)s_h4;
    float* sz1  = (float*)s_z1;
    float* sz2  = (float*)s_z2;

    const int i  = threadIdx.x;      // 0..63 : owns z-row i
    const int r  = i & 15;           // W3 row handled (partially) by this thread
    const int cs = (i >> 4) * 16;    // W3 column slice start

    // --- register-resident weights ---
    unsigned long long w1h[8];
    {
        const float* w = W1 + i * (HDIM + UDIM);
#pragma unroll
        for (int k = 0; k < 8; k++) w1h[k] = pk2(w[2 * k], w[2 * k + 1]);
    }
    unsigned long long w2p[32];
    {
        const float4* w = (const float4*)(W2 + i * HID);
#pragma unroll
        for (int k = 0; k < 16; k++) {
            float4 v = w[k];
            w2p[2 * k]     = pk2(v.x, v.y);
            w2p[2 * k + 1] = pk2(v.z, v.w);
        }
    }
    unsigned long long w3p[8];
    {
        const float4* w = (const float4*)(W3 + r * HID + cs);
#pragma unroll
        for (int k = 0; k < 4; k++) {
            float4 v = w[k];
            w3p[2 * k]     = pk2(v.x, v.y);
            w3p[2 * k + 1] = pk2(v.z, v.w);
        }
    }
    const float b2r = b2v[i];
    float hreg = 0.0f, b3r = 0.0f;
    if (i < HDIM) {
        hreg = h0[i];
        b3r  = b3[i];
        sh_h[i] = hreg;
        g_h[i]  = hreg;   // h_0 for the readout post-pass
    }
    float pu_cur = g_pu[i];
    const float dtc = DTC;
    __syncthreads();

    for (int t = 0; t < T; t++) {
        // ---- stage 1: z1 = tanh(W1h @ h + pu[t]) ----
        unsigned long long acc = 0ull;
        const float2* h2 = (const float2*)sh_h;
#pragma unroll
        for (int k = 0; k < 8; k++) {
            float2 hv = h2[k];
            acc = ffma2(w1h[k], pk2(hv.x, hv.y), acc);
        }
        float ax, ay;
        upk2(acc, ax, ay);
        float pre1 = ax + ay + pu_cur;

        // prefetch next step's input projection (hides LDG latency under the step)
        float pu_next = 0.0f;
        if (t + 1 < T) pu_next = g_pu[(t + 1) * HID + i];

        sz1[i] = tanhf(pre1);
        __syncthreads();

        // ---- stage 2: z2 = tanh(W2 @ z1 + b2) ----
        unsigned long long a0 = 0ull, a1 = 0ull;
#pragma unroll
        for (int k = 0; k < 16; k++) {
            float4 v = s_z1[k];
            a0 = ffma2(w2p[2 * k],     pk2(v.x, v.y), a0);
            a1 = ffma2(w2p[2 * k + 1], pk2(v.z, v.w), a1);
        }
        float s0, s1, s2, s3;
        upk2(a0, s0, s1);
        upk2(a1, s2, s3);
        sz2[i] = tanhf((s0 + s1) + (s2 + s3) + b2r);
        __syncthreads();

        // ---- stage 3: dh partial = W3[r, cs:cs+16] @ z2[cs:cs+16] ----
        unsigned long long p = 0ull;
        const float4* z2v = (const float4*)(sz2 + cs);
#pragma unroll
        for (int k = 0; k < 4; k++) {
            float4 v = z2v[k];
            p = ffma2(w3p[2 * k],     pk2(v.x, v.y), p);
            p = ffma2(w3p[2 * k + 1], pk2(v.z, v.w), p);
        }
        float px, py;
        upk2(p, px, py);
        float ps = px + py;
        // pair columns within each warp: lane l gets l's + (l+16)'s slice
        ps += __shfl_xor_sync(0xffffffffu, ps, 16);
        if (i >= 32 && i < 48) s_dhp[i - 32] = ps;   // warp1 half (cols 32..63)
        __syncthreads();

        // ---- stage 4: Euler update on warp0 lanes 0..15 ----
        if (i < HDIM) {
            float dh = ps + s_dhp[i] + b3r;
            hreg = fmaf(dh, dtc, hreg);
            sh_h[i] = hreg;
            if (t + 1 < T) g_h[(t + 1) * HDIM + i] = hreg;  // h_{t+1} for readouts
            else           out[3 * T + i] = hreg;           // final hT
        }
        __syncthreads();
        pu_cur = pu_next;
    }
}

// ---------- post-pass: readouts for all t in parallel ----------
__global__ void post_kernel(const float* __restrict__ wd, const float* __restrict__ bd,
                            const float* __restrict__ wt, const float* __restrict__ bt,
                            const float* __restrict__ wc, const float* __restrict__ bc,
                            float* __restrict__ out, int T) {
    int t = blockIdx.x * blockDim.x + threadIdx.x;
    if (t >= T) return;
    const float4* hv = (const float4*)(g_h + t * HDIM);
    float d  = bd[0];
    float tx = bt[0];
    float ll = bc[0];
#pragma unroll
    for (int k = 0; k < 4; k++) {
        float4 h = hv[k];
        float4 a = ((const float4*)wd)[k];
        float4 b = ((const float4*)wt)[k];
        float4 c = ((const float4*)wc)[k];
        d  = fmaf(h.x, a.x, d);  d  = fmaf(h.y, a.y, d);
        d  = fmaf(h.z, a.z, d);  d  = fmaf(h.w, a.w, d);
        tx = fmaf(h.x, b.x, tx); tx = fmaf(h.y, b.y, tx);
        tx = fmaf(h.z, b.z, tx); tx = fmaf(h.w, b.w, tx);
        ll = fmaf(h.x, c.x, ll); ll = fmaf(h.y, c.y, ll);
        ll = fmaf(h.z, c.z, ll); ll = fmaf(h.w, c.w, ll);
    }
    out[t]         = d;
    out[T + t]     = tx;
    out[2 * T + t] = ll;
}

extern "C" void kernel_launch(void* const* d_in, const int* in_sizes, int n_in,
                              void* d_out, int out_size) {
    const float* U  = (const float*)d_in[0];
    const float* W1 = (const float*)d_in[1];
    const float* b1 = (const float*)d_in[2];
    const float* W2 = (const float*)d_in[3];
    const float* b2 = (const float*)d_in[4];
    const float* W3 = (const float*)d_in[5];
    const float* b3 = (const float*)d_in[6];
    const float* wd = (const float*)d_in[7];
    const float* bd = (const float*)d_in[8];
    const float* wt = (const float*)d_in[9];
    const float* bt = (const float*)d_in[10];
    const float* wc = (const float*)d_in[11];
    const float* bc = (const float*)d_in[12];
    const float* h0 = (const float*)d_in[13];
    float* out = (float*)d_out;

    int T = in_sizes[0] / UDIM;
    if (T > TMAX) T = TMAX;

    int n = T * HID;
    pre_kernel<<<(n + 255) / 256, 256>>>(U, W1, b1, T);
    seq_kernel<<<1, 64>>>(W1, b2, W2, W3, b3, h0, out, T);
    post_kernel<<<(T + 127) / 128, 128>>>(wd, bd, wt, bt, wc, bc, out, T);
}